// round 3
// baseline (speedup 1.0000x reference)
#include <cuda_runtime.h>
#include <math.h>

// ---------------- problem constants ----------------
#define BQ     4
#define SEQ    4096
#define DIMX   1024
#define HEADS  16
#define DH     64
#define DI     1024
#define MROWS  (BQ*SEQ)     // 16384
#define QKVN   3072

typedef unsigned long long u64;

// ---------------- scratch (device globals; no allocation) ----------------
__device__ float g_xn [(size_t)MROWS * DIMX];   //  64 MB
__device__ float g_qkv[(size_t)MROWS * QKVN];   // 192 MB
__device__ float g_ao [(size_t)MROWS * DI];     //  64 MB
__device__ float g_sim [64 * 64 * 64];          // raw Gram per (b,h)
__device__ float g_attn[64 * 64 * 64];
__device__ float g_ssq[64 * 64];                // sum q^2 per (bh, d)
__device__ float g_ssk[64 * 64];                // sum k^2 per (bh, e)

// ---------------- f32x2 helpers ----------------
__device__ __forceinline__ u64 pk2(float lo, float hi) {
    u64 r;
    asm("mov.b64 %0, {%1, %2};" : "=l"(r)
        : "r"(__float_as_uint(lo)), "r"(__float_as_uint(hi)));
    return r;
}
__device__ __forceinline__ u64 pkdup(float v) {
    u64 r;
    asm("mov.b64 %0, {%1, %1};" : "=l"(r) : "r"(__float_as_uint(v)));
    return r;
}
__device__ __forceinline__ void unpk2(u64 u, float& lo, float& hi) {
    unsigned int a, b;
    asm("mov.b64 {%0, %1}, %2;" : "=r"(a), "=r"(b) : "l"(u));
    lo = __uint_as_float(a);
    hi = __uint_as_float(b);
}
#define FFMA2(c, a, b) asm("fma.rn.f32x2 %0, %1, %2, %0;" : "+l"(c) : "l"(a), "l"(b))

// ---------------- kernel 0: zero accumulators ----------------
__global__ void k_zero() {
    int i = blockIdx.x * 256 + threadIdx.x;
    if (i < 64 * 64 * 64) g_sim[i] = 0.0f;
    if (i < 64 * 64) { g_ssq[i] = 0.0f; g_ssk[i] = 0.0f; }
}

// ---------------- kernel 1: RMSNorm (F.normalize * sqrt(dim) * gamma) ----------------
__global__ __launch_bounds__(256) void k_rmsnorm(const float* __restrict__ x,
                                                 const float* __restrict__ gamma) {
    int row = blockIdx.x;
    int t = threadIdx.x;
    const float4* xr = (const float4*)(x + (size_t)row * DIMX);
    float4 v = xr[t];
    float ss = v.x * v.x + v.y * v.y + v.z * v.z + v.w * v.w;
    __shared__ float red[8];
    #pragma unroll
    for (int o = 16; o; o >>= 1) ss += __shfl_xor_sync(0xffffffffu, ss, o);
    if ((t & 31) == 0) red[t >> 5] = ss;
    __syncthreads();
    if (t < 8) {
        float s2 = red[t];
        #pragma unroll
        for (int o = 4; o; o >>= 1) s2 += __shfl_xor_sync(0xffu, s2, o);
        if (t == 0) red[0] = s2;
    }
    __syncthreads();
    float norm = sqrtf(red[0]);
    float scale = 32.0f / fmaxf(norm, 1e-12f);
    float4 g = ((const float4*)gamma)[t];
    float4 o;
    o.x = v.x * scale * g.x;
    o.y = v.y * scale * g.y;
    o.z = v.z * scale * g.z;
    o.w = v.w * scale * g.w;
    ((float4*)(g_xn + (size_t)row * DIMX))[t] = o;
}

// ---------------- GEMM body: C[M,NDIM] = A[M,1024] @ B[1024,NDIM], fp32 via f32x2 ----------------
// 128x128 block tile, BK=16, 256 threads, 8x8 per-thread microtile, double-buffered smem.
template <int NDIM>
__device__ __forceinline__ void gemm_body(const float* __restrict__ A,
                                          const float* __restrict__ Bm,
                                          float* __restrict__ C) {
    constexpr int K = 1024;
    __shared__ float As[2][16][128];
    __shared__ float Bs[2][16][128];

    const int tid = threadIdx.x;
    const int tx = tid & 15;
    const int ty = tid >> 4;
    const int row0 = blockIdx.y * 128;
    const int col0 = blockIdx.x * 128;

    const int ar = tid >> 2;          // 0..63 (second load covers 64..127)
    const int ak = (tid & 3) * 4;     // 0,4,8,12
    const int bk = tid >> 5;          // 0..7  (second load covers 8..15)
    const int bn = (tid & 31) * 4;    // 0..124

    const float* Aptr = A + (size_t)(row0 + ar) * K + ak;
    const float* Bptr = Bm + (size_t)bk * NDIM + col0 + bn;

    u64 acc[8][4];
    #pragma unroll
    for (int i = 0; i < 8; i++)
        #pragma unroll
        for (int j = 0; j < 4; j++) acc[i][j] = 0ull;

    float4 a0 = *(const float4*)Aptr;
    float4 a1 = *(const float4*)(Aptr + (size_t)64 * K);
    float4 b0 = *(const float4*)Bptr;
    float4 b1 = *(const float4*)(Bptr + (size_t)8 * NDIM);

    As[0][ak + 0][ar] = a0.x; As[0][ak + 1][ar] = a0.y;
    As[0][ak + 2][ar] = a0.z; As[0][ak + 3][ar] = a0.w;
    As[0][ak + 0][64 + ar] = a1.x; As[0][ak + 1][64 + ar] = a1.y;
    As[0][ak + 2][64 + ar] = a1.z; As[0][ak + 3][64 + ar] = a1.w;
    *(float4*)&Bs[0][bk][bn] = b0;
    *(float4*)&Bs[0][bk + 8][bn] = b1;
    __syncthreads();

    const int NT = K / 16;
    for (int t = 0; t < NT; t++) {
        const int cur = t & 1;
        if (t + 1 < NT) {
            const float* Ap = A + (size_t)(row0 + ar) * K + (t + 1) * 16 + ak;
            a0 = *(const float4*)Ap;
            a1 = *(const float4*)(Ap + (size_t)64 * K);
            const float* Bp = Bm + (size_t)((t + 1) * 16 + bk) * NDIM + col0 + bn;
            b0 = *(const float4*)Bp;
            b1 = *(const float4*)(Bp + (size_t)8 * NDIM);
        }
        #pragma unroll
        for (int k = 0; k < 16; k++) {
            float4 av0 = *(const float4*)&As[cur][k][ty * 4];
            float4 av1 = *(const float4*)&As[cur][k][64 + ty * 4];
            float4 bv0 = *(const float4*)&Bs[cur][k][tx * 4];
            float4 bv1 = *(const float4*)&Bs[cur][k][64 + tx * 4];
            u64 bp0 = pk2(bv0.x, bv0.y), bp1 = pk2(bv0.z, bv0.w);
            u64 bp2 = pk2(bv1.x, bv1.y), bp3 = pk2(bv1.z, bv1.w);
            float a[8] = {av0.x, av0.y, av0.z, av0.w, av1.x, av1.y, av1.z, av1.w};
            #pragma unroll
            for (int i = 0; i < 8; i++) {
                u64 ap = pkdup(a[i]);
                FFMA2(acc[i][0], ap, bp0);
                FFMA2(acc[i][1], ap, bp1);
                FFMA2(acc[i][2], ap, bp2);
                FFMA2(acc[i][3], ap, bp3);
            }
        }
        if (t + 1 < NT) {
            __syncthreads();
            const int nxt = cur ^ 1;
            As[nxt][ak + 0][ar] = a0.x; As[nxt][ak + 1][ar] = a0.y;
            As[nxt][ak + 2][ar] = a0.z; As[nxt][ak + 3][ar] = a0.w;
            As[nxt][ak + 0][64 + ar] = a1.x; As[nxt][ak + 1][64 + ar] = a1.y;
            As[nxt][ak + 2][64 + ar] = a1.z; As[nxt][ak + 3][64 + ar] = a1.w;
            *(float4*)&Bs[nxt][bk][bn] = b0;
            *(float4*)&Bs[nxt][bk + 8][bn] = b1;
            __syncthreads();
        }
    }

    #pragma unroll
    for (int i = 0; i < 8; i++) {
        int r = row0 + ((i < 4) ? (ty * 4 + i) : (64 + ty * 4 + i - 4));
        float x0, x1, x2, x3, x4, x5, x6, x7;
        unpk2(acc[i][0], x0, x1);
        unpk2(acc[i][1], x2, x3);
        unpk2(acc[i][2], x4, x5);
        unpk2(acc[i][3], x6, x7);
        float4 o0 = make_float4(x0, x1, x2, x3);
        float4 o1 = make_float4(x4, x5, x6, x7);
        *(float4*)&C[(size_t)r * NDIM + col0 + tx * 4] = o0;
        *(float4*)&C[(size_t)r * NDIM + col0 + 64 + tx * 4] = o1;
    }
}

__global__ __launch_bounds__(256) void k_gemm_qkv(const float* __restrict__ w) {
    gemm_body<QKVN>(g_xn, w, g_qkv);
}
__global__ __launch_bounds__(256) void k_gemm_out(const float* __restrict__ w,
                                                  float* __restrict__ out) {
    gemm_body<DI>(g_ao, w, out);
}

// ---------------- kernel 3a: raw Gram sim[d][e] += q.k over n-split; also sumsq ----------------
__global__ __launch_bounds__(256) void k_sim() {
    const int bh = blockIdx.x;        // b*16 + h
    const int split = blockIdx.y;     // 0..7, 512 n each
    const int b = bh >> 4, h = bh & 15;
    const int tid = threadIdx.x;
    const int tx = tid & 15, ty = tid >> 4;

    __shared__ float qs[32][64];
    __shared__ float ks[32][64];

    float acc[4][4];
    #pragma unroll
    for (int i = 0; i < 4; i++)
        #pragma unroll
        for (int j = 0; j < 4; j++) acc[i][j] = 0.0f;

    float sq0 = 0, sq1 = 0, sq2 = 0, sq3 = 0;
    float sk0 = 0, sk1 = 0, sk2 = 0, sk3 = 0;

    const size_t basep = ((size_t)b * SEQ) * QKVN + (size_t)h * DH;
    const int nnA = tid >> 4;          // 0..15
    const int dA = (tid & 15) * 4;     // 0..60

    for (int t = 0; t < 16; t++) {
        const int n = split * 512 + t * 32;
        const float* qg = g_qkv + basep + (size_t)n * QKVN;

        float4 q0 = *(const float4*)(qg + (size_t)nnA * QKVN + dA);
        float4 q1 = *(const float4*)(qg + (size_t)(nnA + 16) * QKVN + dA);
        float4 k0 = *(const float4*)(qg + DI + (size_t)nnA * QKVN + dA);
        float4 k1 = *(const float4*)(qg + DI + (size_t)(nnA + 16) * QKVN + dA);

        sq0 += q0.x * q0.x + q1.x * q1.x;
        sq1 += q0.y * q0.y + q1.y * q1.y;
        sq2 += q0.z * q0.z + q1.z * q1.z;
        sq3 += q0.w * q0.w + q1.w * q1.w;
        sk0 += k0.x * k0.x + k1.x * k1.x;
        sk1 += k0.y * k0.y + k1.y * k1.y;
        sk2 += k0.z * k0.z + k1.z * k1.z;
        sk3 += k0.w * k0.w + k1.w * k1.w;

        __syncthreads();
        *(float4*)&qs[nnA][dA] = q0;
        *(float4*)&qs[nnA + 16][dA] = q1;
        *(float4*)&ks[nnA][dA] = k0;
        *(float4*)&ks[nnA + 16][dA] = k1;
        __syncthreads();

        #pragma unroll 8
        for (int nn = 0; nn < 32; nn++) {
            float4 qa = *(const float4*)&qs[nn][ty * 4];
            float4 kb = *(const float4*)&ks[nn][tx * 4];
            float aa[4] = {qa.x, qa.y, qa.z, qa.w};
            float bb[4] = {kb.x, kb.y, kb.z, kb.w};
            #pragma unroll
            for (int i = 0; i < 4; i++)
                #pragma unroll
                for (int j = 0; j < 4; j++)
                    acc[i][j] = fmaf(aa[i], bb[j], acc[i][j]);
        }
    }

    float* simp = g_sim + bh * 4096;
    #pragma unroll
    for (int i = 0; i < 4; i++)
        #pragma unroll
        for (int j = 0; j < 4; j++)
            atomicAdd(&simp[(ty * 4 + i) * 64 + tx * 4 + j], acc[i][j]);

    atomicAdd(&g_ssq[bh * 64 + dA + 0], sq0);
    atomicAdd(&g_ssq[bh * 64 + dA + 1], sq1);
    atomicAdd(&g_ssq[bh * 64 + dA + 2], sq2);
    atomicAdd(&g_ssq[bh * 64 + dA + 3], sq3);
    atomicAdd(&g_ssk[bh * 64 + dA + 0], sk0);
    atomicAdd(&g_ssk[bh * 64 + dA + 1], sk1);
    atomicAdd(&g_ssk[bh * 64 + dA + 2], sk2);
    atomicAdd(&g_ssk[bh * 64 + dA + 3], sk3);
}

// ---------------- kernel 3b: scale + softmax over e ----------------
__global__ void k_softmax(const float* __restrict__ temperature) {
    const int bh = blockIdx.x;
    const int d = threadIdx.x;  // 64 threads
    const int h = bh & 15;
    const float tscale = 8.0f * expf(temperature[h]);

    __shared__ float rk[64];
    rk[d] = 1.0f / fmaxf(sqrtf(g_ssk[bh * 64 + d]), 1e-12f);
    __syncthreads();

    const float rq = 1.0f / fmaxf(sqrtf(g_ssq[bh * 64 + d]), 1e-12f);
    const float* srow = g_sim + bh * 4096 + d * 64;

    float s[64];
    float mx = -1e30f;
    #pragma unroll
    for (int e = 0; e < 64; e++) {
        s[e] = srow[e] * tscale * rq * rk[e];
        mx = fmaxf(mx, s[e]);
    }
    float sum = 0.0f;
    #pragma unroll
    for (int e = 0; e < 64; e++) {
        s[e] = expf(s[e] - mx);
        sum += s[e];
    }
    const float inv = 1.0f / sum;
    float* arow = g_attn + bh * 4096 + d * 64;
    #pragma unroll
    for (int e = 0; e < 64; e++) arow[e] = s[e] * inv;
}

// ---------------- kernel 3c: out[d][n] = sum_e attn[d][e] v[e][n]; write (b,n,h*64+d) ----------------
__global__ __launch_bounds__(256) void k_av() {
    const int bh = blockIdx.x;
    const int split = blockIdx.y;  // 0..7
    const int b = bh >> 4, h = bh & 15;
    const int tid = threadIdx.x;
    const int tx = tid & 15, ty = tid >> 4;

    __shared__ float at[64][68];  // attn transposed: at[e][d]
    __shared__ float vt[64][68];  // v transposed:    vt[e][nn]

    const float* ap = g_attn + bh * 4096;
    #pragma unroll
    for (int i = 0; i < 16; i++) {
        int idx = tid + i * 256;
        at[idx & 63][idx >> 6] = ap[idx];
    }

    const size_t vbase = ((size_t)b * SEQ) * QKVN + 2 * DI + (size_t)h * DH;

    for (int t = 0; t < 8; t++) {
        const int n0 = split * 512 + t * 64;
        __syncthreads();
        #pragma unroll
        for (int i = 0; i < 4; i++) {
            int f = tid + i * 256;
            int nn = f >> 4;
            int ec = (f & 15) * 4;
            float4 v4 = *(const float4*)(g_qkv + vbase + (size_t)(n0 + nn) * QKVN + ec);
            vt[ec + 0][nn] = v4.x;
            vt[ec + 1][nn] = v4.y;
            vt[ec + 2][nn] = v4.z;
            vt[ec + 3][nn] = v4.w;
        }
        __syncthreads();

        float acc[4][4];  // [nn j][d i]
        #pragma unroll
        for (int j = 0; j < 4; j++)
            #pragma unroll
            for (int i = 0; i < 4; i++) acc[j][i] = 0.0f;

        #pragma unroll 8
        for (int e = 0; e < 64; e++) {
            float4 a4 = *(const float4*)&at[e][tx * 4];  // d
            float4 v4 = *(const float4*)&vt[e][ty * 4];  // nn
            float aa[4] = {a4.x, a4.y, a4.z, a4.w};
            float vv[4] = {v4.x, v4.y, v4.z, v4.w};
            #pragma unroll
            for (int j = 0; j < 4; j++)
                #pragma unroll
                for (int i = 0; i < 4; i++)
                    acc[j][i] = fmaf(vv[j], aa[i], acc[j][i]);
        }

        #pragma unroll
        for (int j = 0; j < 4; j++) {
            int n = n0 + ty * 4 + j;
            float4 o = make_float4(acc[j][0], acc[j][1], acc[j][2], acc[j][3]);
            *(float4*)&g_ao[(size_t)(b * SEQ + n) * DI + h * DH + tx * 4] = o;
        }
    }
}

// ---------------- launch ----------------
extern "C" void kernel_launch(void* const* d_in, const int* in_sizes, int n_in,
                              void* d_out, int out_size) {
    const float* x = (const float*)d_in[0];
    const float* gamma = (const float*)d_in[1];
    const float* w_qkv = (const float*)d_in[2];
    const float* temperature = (const float*)d_in[3];
    const float* w_out = (const float*)d_in[4];
    float* out = (float*)d_out;

    k_zero<<<1024, 256>>>();
    k_rmsnorm<<<MROWS, 256>>>(x, gamma);
    k_gemm_qkv<<<dim3(QKVN / 128, MROWS / 128), 256>>>(w_qkv);
    k_sim<<<dim3(64, 8), 256>>>();
    k_softmax<<<64, 64>>>(temperature);
    k_av<<<dim3(64, 8), 256>>>();
    k_gemm_out<<<dim3(DI / 128, MROWS / 128), 256>>>(w_out, out);
}

// round 7
// speedup vs baseline: 1.3180x; 1.3180x over previous
#include <cuda_runtime.h>
#include <math.h>

// ---------------- problem constants ----------------
#define BQ     4
#define SEQ    4096
#define DIMX   1024
#define HEADS  16
#define DH     64
#define DI     1024
#define MROWS  (BQ*SEQ)     // 16384
#define QKVN   3072

typedef unsigned long long u64;

// ---------------- scratch (device globals; no allocation) ----------------
__device__ float g_xn [(size_t)MROWS * DIMX];   //  64 MB
__device__ float g_qkv[(size_t)MROWS * QKVN];   // 192 MB
__device__ float g_ao [(size_t)MROWS * DI];     //  64 MB
__device__ float g_sim [64 * 64 * 64];          // raw Gram per (b,h)
__device__ float g_attn[64 * 64 * 64];
__device__ float g_ssq[64 * 64];                // sum q^2 per (bh, d)
__device__ float g_ssk[64 * 64];                // sum k^2 per (bh, e)

// ---------------- f32x2 helpers ----------------
__device__ __forceinline__ u64 pk2(float lo, float hi) {
    u64 r;
    asm("mov.b64 %0, {%1, %2};" : "=l"(r)
        : "r"(__float_as_uint(lo)), "r"(__float_as_uint(hi)));
    return r;
}
__device__ __forceinline__ u64 pkdup(float v) {
    u64 r;
    asm("mov.b64 %0, {%1, %1};" : "=l"(r) : "r"(__float_as_uint(v)));
    return r;
}
__device__ __forceinline__ void unpk2(u64 u, float& lo, float& hi) {
    unsigned int a, b;
    asm("mov.b64 {%0, %1}, %2;" : "=r"(a), "=r"(b) : "l"(u));
    lo = __uint_as_float(a);
    hi = __uint_as_float(b);
}
#define FFMA2(c, a, b) asm("fma.rn.f32x2 %0, %1, %2, %0;" : "+l"(c) : "l"(a), "l"(b))

// ---------------- kernel 0: zero accumulators ----------------
__global__ void k_zero() {
    int i = blockIdx.x * 256 + threadIdx.x;
    if (i < 64 * 64 * 64) g_sim[i] = 0.0f;
    if (i < 64 * 64) { g_ssq[i] = 0.0f; g_ssk[i] = 0.0f; }
}

// ---------------- kernel 1: RMSNorm (F.normalize * sqrt(dim) * gamma) ----------------
__global__ __launch_bounds__(256) void k_rmsnorm(const float* __restrict__ x,
                                                 const float* __restrict__ gamma) {
    int row = blockIdx.x;
    int t = threadIdx.x;
    const float4* xr = (const float4*)(x + (size_t)row * DIMX);
    float4 v = xr[t];
    float ss = v.x * v.x + v.y * v.y + v.z * v.z + v.w * v.w;
    __shared__ float red[8];
    #pragma unroll
    for (int o = 16; o; o >>= 1) ss += __shfl_xor_sync(0xffffffffu, ss, o);
    if ((t & 31) == 0) red[t >> 5] = ss;
    __syncthreads();
    if (t < 8) {
        float s2 = red[t];
        #pragma unroll
        for (int o = 4; o; o >>= 1) s2 += __shfl_xor_sync(0xffu, s2, o);
        if (t == 0) red[0] = s2;
    }
    __syncthreads();
    float norm = sqrtf(red[0]);
    float scale = 32.0f / fmaxf(norm, 1e-12f);
    float4 g = ((const float4*)gamma)[t];
    float4 o;
    o.x = v.x * scale * g.x;
    o.y = v.y * scale * g.y;
    o.z = v.z * scale * g.z;
    o.w = v.w * scale * g.w;
    ((float4*)(g_xn + (size_t)row * DIMX))[t] = o;
}

// ---------------- GEMM body: C[M,NDIM] = A[M,1024] @ B[1024,NDIM], fp32 via f32x2 ----------------
// 128x128 block tile, BK=16, 256 threads, 8x8 per-thread microtile,
// double-buffered smem with a SINGLE barrier per k-chunk, 2 blocks/SM.
template <int NDIM>
__device__ __forceinline__ void gemm_body(const float* __restrict__ A,
                                          const float* __restrict__ Bm,
                                          float* __restrict__ C) {
    constexpr int K = 1024;
    __shared__ float As[2][16][128];
    __shared__ float Bs[2][16][128];

    const int tid = threadIdx.x;
    const int tx = tid & 15;
    const int ty = tid >> 4;
    const int row0 = blockIdx.y * 128;
    const int col0 = blockIdx.x * 128;

    const int ar = tid >> 2;          // 0..63 (second load covers 64..127)
    const int ak = (tid & 3) * 4;     // 0,4,8,12
    const int bk = tid >> 5;          // 0..7  (second load covers 8..15)
    const int bn = (tid & 31) * 4;    // 0..124

    const float* Aptr = A + (size_t)(row0 + ar) * K + ak;
    const float* Bptr = Bm + (size_t)bk * NDIM + col0 + bn;

    u64 acc[8][4];
    #pragma unroll
    for (int i = 0; i < 8; i++)
        #pragma unroll
        for (int j = 0; j < 4; j++) acc[i][j] = 0ull;

    float4 a0 = *(const float4*)Aptr;
    float4 a1 = *(const float4*)(Aptr + (size_t)64 * K);
    float4 b0 = *(const float4*)Bptr;
    float4 b1 = *(const float4*)(Bptr + (size_t)8 * NDIM);

    As[0][ak + 0][ar] = a0.x; As[0][ak + 1][ar] = a0.y;
    As[0][ak + 2][ar] = a0.z; As[0][ak + 3][ar] = a0.w;
    As[0][ak + 0][64 + ar] = a1.x; As[0][ak + 1][64 + ar] = a1.y;
    As[0][ak + 2][64 + ar] = a1.z; As[0][ak + 3][64 + ar] = a1.w;
    *(float4*)&Bs[0][bk][bn] = b0;
    *(float4*)&Bs[0][bk + 8][bn] = b1;
    __syncthreads();

    const int NT = K / 16;
    for (int t = 0; t < NT; t++) {
        const int cur = t & 1;
        if (t + 1 < NT) {
            const float* Ap = A + (size_t)(row0 + ar) * K + (t + 1) * 16 + ak;
            a0 = *(const float4*)Ap;
            a1 = *(const float4*)(Ap + (size_t)64 * K);
            const float* Bp = Bm + (size_t)((t + 1) * 16 + bk) * NDIM + col0 + bn;
            b0 = *(const float4*)Bp;
            b1 = *(const float4*)(Bp + (size_t)8 * NDIM);
        }
        #pragma unroll
        for (int k = 0; k < 16; k++) {
            float4 av0 = *(const float4*)&As[cur][k][ty * 4];
            float4 av1 = *(const float4*)&As[cur][k][64 + ty * 4];
            float4 bv0 = *(const float4*)&Bs[cur][k][tx * 4];
            float4 bv1 = *(const float4*)&Bs[cur][k][64 + tx * 4];
            u64 bp0 = pk2(bv0.x, bv0.y), bp1 = pk2(bv0.z, bv0.w);
            u64 bp2 = pk2(bv1.x, bv1.y), bp3 = pk2(bv1.z, bv1.w);
            float a[8] = {av0.x, av0.y, av0.z, av0.w, av1.x, av1.y, av1.z, av1.w};
            #pragma unroll
            for (int i = 0; i < 8; i++) {
                u64 ap = pkdup(a[i]);
                FFMA2(acc[i][0], ap, bp0);
                FFMA2(acc[i][1], ap, bp1);
                FFMA2(acc[i][2], ap, bp2);
                FFMA2(acc[i][3], ap, bp3);
            }
        }
        if (t + 1 < NT) {
            // single-barrier double buffering: writes go to the buffer all warps
            // finished reading one full iteration (one barrier) ago.
            const int nxt = cur ^ 1;
            As[nxt][ak + 0][ar] = a0.x; As[nxt][ak + 1][ar] = a0.y;
            As[nxt][ak + 2][ar] = a0.z; As[nxt][ak + 3][ar] = a0.w;
            As[nxt][ak + 0][64 + ar] = a1.x; As[nxt][ak + 1][64 + ar] = a1.y;
            As[nxt][ak + 2][64 + ar] = a1.z; As[nxt][ak + 3][64 + ar] = a1.w;
            *(float4*)&Bs[nxt][bk][bn] = b0;
            *(float4*)&Bs[nxt][bk + 8][bn] = b1;
            __syncthreads();
        }
    }

    #pragma unroll
    for (int i = 0; i < 8; i++) {
        int r = row0 + ((i < 4) ? (ty * 4 + i) : (64 + ty * 4 + i - 4));
        float x0, x1, x2, x3, x4, x5, x6, x7;
        unpk2(acc[i][0], x0, x1);
        unpk2(acc[i][1], x2, x3);
        unpk2(acc[i][2], x4, x5);
        unpk2(acc[i][3], x6, x7);
        float4 o0 = make_float4(x0, x1, x2, x3);
        float4 o1 = make_float4(x4, x5, x6, x7);
        *(float4*)&C[(size_t)r * NDIM + col0 + tx * 4] = o0;
        *(float4*)&C[(size_t)r * NDIM + col0 + 64 + tx * 4] = o1;
    }
}

__global__ __launch_bounds__(256, 2) void k_gemm_qkv(const float* __restrict__ w) {
    gemm_body<QKVN>(g_xn, w, g_qkv);
}
__global__ __launch_bounds__(256, 2) void k_gemm_out(const float* __restrict__ w,
                                                     float* __restrict__ out) {
    gemm_body<DI>(g_ao, w, out);
}

// ---------------- kernel 3a: raw Gram sim[d][e] += q.k over n-split; also sumsq ----------------
// 16 splits of 256 n each (occupancy was grid-limited at 8 splits).
__global__ __launch_bounds__(256) void k_sim() {
    const int bh = blockIdx.x;        // b*16 + h
    const int split = blockIdx.y;     // 0..15, 256 n each
    const int b = bh >> 4, h = bh & 15;
    const int tid = threadIdx.x;
    const int tx = tid & 15, ty = tid >> 4;

    __shared__ float qs[32][64];
    __shared__ float ks[32][64];

    float acc[4][4];
    #pragma unroll
    for (int i = 0; i < 4; i++)
        #pragma unroll
        for (int j = 0; j < 4; j++) acc[i][j] = 0.0f;

    float sq0 = 0, sq1 = 0, sq2 = 0, sq3 = 0;
    float sk0 = 0, sk1 = 0, sk2 = 0, sk3 = 0;

    const size_t basep = ((size_t)b * SEQ) * QKVN + (size_t)h * DH;
    const int nnA = tid >> 4;          // 0..15
    const int dA = (tid & 15) * 4;     // 0..60

    for (int t = 0; t < 8; t++) {
        const int n = split * 256 + t * 32;
        const float* qg = g_qkv + basep + (size_t)n * QKVN;

        float4 q0 = *(const float4*)(qg + (size_t)nnA * QKVN + dA);
        float4 q1 = *(const float4*)(qg + (size_t)(nnA + 16) * QKVN + dA);
        float4 k0 = *(const float4*)(qg + DI + (size_t)nnA * QKVN + dA);
        float4 k1 = *(const float4*)(qg + DI + (size_t)(nnA + 16) * QKVN + dA);

        sq0 += q0.x * q0.x + q1.x * q1.x;
        sq1 += q0.y * q0.y + q1.y * q1.y;
        sq2 += q0.z * q0.z + q1.z * q1.z;
        sq3 += q0.w * q0.w + q1.w * q1.w;
        sk0 += k0.x * k0.x + k1.x * k1.x;
        sk1 += k0.y * k0.y + k1.y * k1.y;
        sk2 += k0.z * k0.z + k1.z * k1.z;
        sk3 += k0.w * k0.w + k1.w * k1.w;

        __syncthreads();
        *(float4*)&qs[nnA][dA] = q0;
        *(float4*)&qs[nnA + 16][dA] = q1;
        *(float4*)&ks[nnA][dA] = k0;
        *(float4*)&ks[nnA + 16][dA] = k1;
        __syncthreads();

        #pragma unroll 8
        for (int nn = 0; nn < 32; nn++) {
            float4 qa = *(const float4*)&qs[nn][ty * 4];
            float4 kb = *(const float4*)&ks[nn][tx * 4];
            float aa[4] = {qa.x, qa.y, qa.z, qa.w};
            float bb[4] = {kb.x, kb.y, kb.z, kb.w};
            #pragma unroll
            for (int i = 0; i < 4; i++)
                #pragma unroll
                for (int j = 0; j < 4; j++)
                    acc[i][j] = fmaf(aa[i], bb[j], acc[i][j]);
        }
    }

    float* simp = g_sim + bh * 4096;
    #pragma unroll
    for (int i = 0; i < 4; i++)
        #pragma unroll
        for (int j = 0; j < 4; j++)
            atomicAdd(&simp[(ty * 4 + i) * 64 + tx * 4 + j], acc[i][j]);

    atomicAdd(&g_ssq[bh * 64 + dA + 0], sq0);
    atomicAdd(&g_ssq[bh * 64 + dA + 1], sq1);
    atomicAdd(&g_ssq[bh * 64 + dA + 2], sq2);
    atomicAdd(&g_ssq[bh * 64 + dA + 3], sq3);
    atomicAdd(&g_ssk[bh * 64 + dA + 0], sk0);
    atomicAdd(&g_ssk[bh * 64 + dA + 1], sk1);
    atomicAdd(&g_ssk[bh * 64 + dA + 2], sk2);
    atomicAdd(&g_ssk[bh * 64 + dA + 3], sk3);
}

// ---------------- kernel 3b: scale + softmax over e ----------------
__global__ void k_softmax(const float* __restrict__ temperature) {
    const int bh = blockIdx.x;
    const int d = threadIdx.x;  // 64 threads
    const int h = bh & 15;
    const float tscale = 8.0f * expf(temperature[h]);

    __shared__ float rk[64];
    rk[d] = 1.0f / fmaxf(sqrtf(g_ssk[bh * 64 + d]), 1e-12f);
    __syncthreads();

    const float rq = 1.0f / fmaxf(sqrtf(g_ssq[bh * 64 + d]), 1e-12f);
    const float* srow = g_sim + bh * 4096 + d * 64;

    float s[64];
    float mx = -1e30f;
    #pragma unroll
    for (int e = 0; e < 64; e++) {
        s[e] = srow[e] * tscale * rq * rk[e];
        mx = fmaxf(mx, s[e]);
    }
    float sum = 0.0f;
    #pragma unroll
    for (int e = 0; e < 64; e++) {
        s[e] = expf(s[e] - mx);
        sum += s[e];
    }
    const float inv = 1.0f / sum;
    float* arow = g_attn + bh * 4096 + d * 64;
    #pragma unroll
    for (int e = 0; e < 64; e++) arow[e] = s[e] * inv;
}

// ---------------- kernel 3c: out[d][n] = sum_e attn[d][e] v[e][n]; write (b,n,h*64+d) ----------------
// 16 splits of 256 n each.
__global__ __launch_bounds__(256) void k_av() {
    const int bh = blockIdx.x;
    const int split = blockIdx.y;  // 0..15
    const int b = bh >> 4, h = bh & 15;
    const int tid = threadIdx.x;
    const int tx = tid & 15, ty = tid >> 4;

    __shared__ float at[64][68];  // attn transposed: at[e][d]
    __shared__ float vt[64][68];  // v transposed:    vt[e][nn]

    const float* ap = g_attn + bh * 4096;
    #pragma unroll
    for (int i = 0; i < 16; i++) {
        int idx = tid + i * 256;
        at[idx & 63][idx >> 6] = ap[idx];
    }

    const size_t vbase = ((size_t)b * SEQ) * QKVN + 2 * DI + (size_t)h * DH;

    for (int t = 0; t < 4; t++) {
        const int n0 = split * 256 + t * 64;
        __syncthreads();
        #pragma unroll
        for (int i = 0; i < 4; i++) {
            int f = tid + i * 256;
            int nn = f >> 4;
            int ec = (f & 15) * 4;
            float4 v4 = *(const float4*)(g_qkv + vbase + (size_t)(n0 + nn) * QKVN + ec);
            vt[ec + 0][nn] = v4.x;
            vt[ec + 1][nn] = v4.y;
            vt[ec + 2][nn] = v4.z;
            vt[ec + 3][nn] = v4.w;
        }
        __syncthreads();

        float acc[4][4];  // [nn j][d i]
        #pragma unroll
        for (int j = 0; j < 4; j++)
            #pragma unroll
            for (int i = 0; i < 4; i++) acc[j][i] = 0.0f;

        #pragma unroll 8
        for (int e = 0; e < 64; e++) {
            float4 a4 = *(const float4*)&at[e][tx * 4];  // d
            float4 v4 = *(const float4*)&vt[e][ty * 4];  // nn
            float aa[4] = {a4.x, a4.y, a4.z, a4.w};
            float vv[4] = {v4.x, v4.y, v4.z, v4.w};
            #pragma unroll
            for (int j = 0; j < 4; j++)
                #pragma unroll
                for (int i = 0; i < 4; i++)
                    acc[j][i] = fmaf(vv[j], aa[i], acc[j][i]);
        }

        #pragma unroll
        for (int j = 0; j < 4; j++) {
            int n = n0 + ty * 4 + j;
            float4 o = make_float4(acc[j][0], acc[j][1], acc[j][2], acc[j][3]);
            *(float4*)&g_ao[(size_t)(b * SEQ + n) * DI + h * DH + tx * 4] = o;
        }
    }
}

// ---------------- launch ----------------
extern "C" void kernel_launch(void* const* d_in, const int* in_sizes, int n_in,
                              void* d_out, int out_size) {
    const float* x = (const float*)d_in[0];
    const float* gamma = (const float*)d_in[1];
    const float* w_qkv = (const float*)d_in[2];
    const float* temperature = (const float*)d_in[3];
    const float* w_out = (const float*)d_in[4];
    float* out = (float*)d_out;

    k_zero<<<1024, 256>>>();
    k_rmsnorm<<<MROWS, 256>>>(x, gamma);
    k_gemm_qkv<<<dim3(QKVN / 128, MROWS / 128), 256>>>(w_qkv);
    k_sim<<<dim3(64, 16), 256>>>();
    k_softmax<<<64, 64>>>(temperature);
    k_av<<<dim3(64, 16), 256>>>();
    k_gemm_out<<<dim3(DI / 128, MROWS / 128), 256>>>(w_out, out);
}

// round 8
// speedup vs baseline: 1.3625x; 1.0338x over previous
#include <cuda_runtime.h>
#include <math.h>

// ---------------- problem constants ----------------
#define BQ     4
#define SEQ    4096
#define DIMX   1024
#define HEADS  16
#define DH     64
#define DI     1024
#define MROWS  (BQ*SEQ)     // 16384
#define QKVN   3072

typedef unsigned long long u64;

// ---------------- scratch (device globals; no allocation) ----------------
__device__ float g_xn [(size_t)MROWS * DIMX];   //  64 MB
__device__ float g_qkv[(size_t)MROWS * QKVN];   // 192 MB
__device__ float g_ao [(size_t)MROWS * DI];     //  64 MB
__device__ float g_sim [64 * 64 * 64];          // raw Gram per (b,h)
__device__ float g_attn[64 * 64 * 64];
__device__ float g_ssq[64 * 64];                // sum q^2 per (bh, d)
__device__ float g_ssk[64 * 64];                // sum k^2 per (bh, e)

// ---------------- f32x2 helpers ----------------
__device__ __forceinline__ u64 pk2(float lo, float hi) {
    u64 r;
    asm("mov.b64 %0, {%1, %2};" : "=l"(r)
        : "r"(__float_as_uint(lo)), "r"(__float_as_uint(hi)));
    return r;
}
__device__ __forceinline__ u64 pkdup(float v) {
    u64 r;
    asm("mov.b64 %0, {%1, %1};" : "=l"(r) : "r"(__float_as_uint(v)));
    return r;
}
__device__ __forceinline__ void unpk2(u64 u, float& lo, float& hi) {
    unsigned int a, b;
    asm("mov.b64 {%0, %1}, %2;" : "=r"(a), "=r"(b) : "l"(u));
    lo = __uint_as_float(a);
    hi = __uint_as_float(b);
}
#define FFMA2(c, a, b) asm("fma.rn.f32x2 %0, %1, %2, %0;" : "+l"(c) : "l"(a), "l"(b))

// ---------------- kernel 1: RMSNorm (+ folded accumulator zeroing) ----------------
__global__ __launch_bounds__(256) void k_rmsnorm(const float* __restrict__ x,
                                                 const float* __restrict__ gamma) {
    int row = blockIdx.x;
    int t = threadIdx.x;

    // fold k_zero: first 1024 blocks clear the small accumulators
    if (row < 1024) {
        int i = row * 256 + t;
        if (i < 64 * 64 * 64) g_sim[i] = 0.0f;
        if (i < 64 * 64) { g_ssq[i] = 0.0f; g_ssk[i] = 0.0f; }
    }

    const float4* xr = (const float4*)(x + (size_t)row * DIMX);
    float4 v = xr[t];
    float ss = v.x * v.x + v.y * v.y + v.z * v.z + v.w * v.w;
    __shared__ float red[8];
    #pragma unroll
    for (int o = 16; o; o >>= 1) ss += __shfl_xor_sync(0xffffffffu, ss, o);
    if ((t & 31) == 0) red[t >> 5] = ss;
    __syncthreads();
    if (t < 8) {
        float s2 = red[t];
        #pragma unroll
        for (int o = 4; o; o >>= 1) s2 += __shfl_xor_sync(0xffu, s2, o);
        if (t == 0) red[0] = s2;
    }
    __syncthreads();
    float norm = sqrtf(red[0]);
    float scale = 32.0f / fmaxf(norm, 1e-12f);
    float4 g = ((const float4*)gamma)[t];
    float4 o;
    o.x = v.x * scale * g.x;
    o.y = v.y * scale * g.y;
    o.z = v.z * scale * g.z;
    o.w = v.w * scale * g.w;
    ((float4*)(g_xn + (size_t)row * DIMX))[t] = o;
}

// ---------------- GEMM body: C[M,NDIM] = A[M,1024] @ B[1024,NDIM], fp32 via f32x2 ----------------
// 128x128 block tile, BK=16, 256 threads, 8x8 per-thread microtile,
// double-buffered smem, single barrier per k-chunk, 2 blocks/SM.
// As row stride padded to 132 floats: staging STS banks = (4k + ar) mod 32 ->
// the 4 lanes sharing ar (consecutive k) hit distinct banks (was 4-way conflict at 128).
#define ASTRIDE 132
template <int NDIM>
__device__ __forceinline__ void gemm_body(const float* __restrict__ A,
                                          const float* __restrict__ Bm,
                                          float* __restrict__ C) {
    constexpr int K = 1024;
    __shared__ float As[2][16][ASTRIDE];
    __shared__ float Bs[2][16][128];

    const int tid = threadIdx.x;
    const int tx = tid & 15;
    const int ty = tid >> 4;
    const int row0 = blockIdx.y * 128;
    const int col0 = blockIdx.x * 128;

    const int ar = tid >> 2;          // 0..63 (second load covers 64..127)
    const int ak = (tid & 3) * 4;     // 0,4,8,12
    const int bk = tid >> 5;          // 0..7  (second load covers 8..15)
    const int bn = (tid & 31) * 4;    // 0..124

    const float* Aptr = A + (size_t)(row0 + ar) * K + ak;
    const float* Bptr = Bm + (size_t)bk * NDIM + col0 + bn;

    u64 acc[8][4];
    #pragma unroll
    for (int i = 0; i < 8; i++)
        #pragma unroll
        for (int j = 0; j < 4; j++) acc[i][j] = 0ull;

    float4 a0 = *(const float4*)Aptr;
    float4 a1 = *(const float4*)(Aptr + (size_t)64 * K);
    float4 b0 = *(const float4*)Bptr;
    float4 b1 = *(const float4*)(Bptr + (size_t)8 * NDIM);

    As[0][ak + 0][ar] = a0.x; As[0][ak + 1][ar] = a0.y;
    As[0][ak + 2][ar] = a0.z; As[0][ak + 3][ar] = a0.w;
    As[0][ak + 0][64 + ar] = a1.x; As[0][ak + 1][64 + ar] = a1.y;
    As[0][ak + 2][64 + ar] = a1.z; As[0][ak + 3][64 + ar] = a1.w;
    *(float4*)&Bs[0][bk][bn] = b0;
    *(float4*)&Bs[0][bk + 8][bn] = b1;
    __syncthreads();

    const int NT = K / 16;
    for (int t = 0; t < NT; t++) {
        const int cur = t & 1;
        if (t + 1 < NT) {
            const float* Ap = A + (size_t)(row0 + ar) * K + (t + 1) * 16 + ak;
            a0 = *(const float4*)Ap;
            a1 = *(const float4*)(Ap + (size_t)64 * K);
            const float* Bp = Bm + (size_t)((t + 1) * 16 + bk) * NDIM + col0 + bn;
            b0 = *(const float4*)Bp;
            b1 = *(const float4*)(Bp + (size_t)8 * NDIM);
        }
        #pragma unroll
        for (int k = 0; k < 16; k++) {
            float4 av0 = *(const float4*)&As[cur][k][ty * 4];
            float4 av1 = *(const float4*)&As[cur][k][64 + ty * 4];
            float4 bv0 = *(const float4*)&Bs[cur][k][tx * 4];
            float4 bv1 = *(const float4*)&Bs[cur][k][64 + tx * 4];
            u64 bp0 = pk2(bv0.x, bv0.y), bp1 = pk2(bv0.z, bv0.w);
            u64 bp2 = pk2(bv1.x, bv1.y), bp3 = pk2(bv1.z, bv1.w);
            float a[8] = {av0.x, av0.y, av0.z, av0.w, av1.x, av1.y, av1.z, av1.w};
            #pragma unroll
            for (int i = 0; i < 8; i++) {
                u64 ap = pkdup(a[i]);
                FFMA2(acc[i][0], ap, bp0);
                FFMA2(acc[i][1], ap, bp1);
                FFMA2(acc[i][2], ap, bp2);
                FFMA2(acc[i][3], ap, bp3);
            }
        }
        if (t + 1 < NT) {
            // single-barrier double buffering: writes go to the buffer all warps
            // finished reading one full iteration (one barrier) ago.
            const int nxt = cur ^ 1;
            As[nxt][ak + 0][ar] = a0.x; As[nxt][ak + 1][ar] = a0.y;
            As[nxt][ak + 2][ar] = a0.z; As[nxt][ak + 3][ar] = a0.w;
            As[nxt][ak + 0][64 + ar] = a1.x; As[nxt][ak + 1][64 + ar] = a1.y;
            As[nxt][ak + 2][64 + ar] = a1.z; As[nxt][ak + 3][64 + ar] = a1.w;
            *(float4*)&Bs[nxt][bk][bn] = b0;
            *(float4*)&Bs[nxt][bk + 8][bn] = b1;
            __syncthreads();
        }
    }

    #pragma unroll
    for (int i = 0; i < 8; i++) {
        int r = row0 + ((i < 4) ? (ty * 4 + i) : (64 + ty * 4 + i - 4));
        float x0, x1, x2, x3, x4, x5, x6, x7;
        unpk2(acc[i][0], x0, x1);
        unpk2(acc[i][1], x2, x3);
        unpk2(acc[i][2], x4, x5);
        unpk2(acc[i][3], x6, x7);
        float4 o0 = make_float4(x0, x1, x2, x3);
        float4 o1 = make_float4(x4, x5, x6, x7);
        *(float4*)&C[(size_t)r * NDIM + col0 + tx * 4] = o0;
        *(float4*)&C[(size_t)r * NDIM + col0 + 64 + tx * 4] = o1;
    }
}

__global__ __launch_bounds__(256, 2) void k_gemm_qkv(const float* __restrict__ w) {
    gemm_body<QKVN>(g_xn, w, g_qkv);
}
__global__ __launch_bounds__(256, 2) void k_gemm_out(const float* __restrict__ w,
                                                     float* __restrict__ out) {
    gemm_body<DI>(g_ao, w, out);
}

// ---------------- kernel 3a: raw Gram sim[d][e] += q.k over n-split; also sumsq ----------------
// 16 splits of 256 n each.
__global__ __launch_bounds__(256) void k_sim() {
    const int bh = blockIdx.x;        // b*16 + h
    const int split = blockIdx.y;     // 0..15, 256 n each
    const int b = bh >> 4, h = bh & 15;
    const int tid = threadIdx.x;
    const int tx = tid & 15, ty = tid >> 4;

    __shared__ float qs[32][64];
    __shared__ float ks[32][64];

    float acc[4][4];
    #pragma unroll
    for (int i = 0; i < 4; i++)
        #pragma unroll
        for (int j = 0; j < 4; j++) acc[i][j] = 0.0f;

    float sq0 = 0, sq1 = 0, sq2 = 0, sq3 = 0;
    float sk0 = 0, sk1 = 0, sk2 = 0, sk3 = 0;

    const size_t basep = ((size_t)b * SEQ) * QKVN + (size_t)h * DH;
    const int nnA = tid >> 4;          // 0..15
    const int dA = (tid & 15) * 4;     // 0..60

    for (int t = 0; t < 8; t++) {
        const int n = split * 256 + t * 32;
        const float* qg = g_qkv + basep + (size_t)n * QKVN;

        float4 q0 = *(const float4*)(qg + (size_t)nnA * QKVN + dA);
        float4 q1 = *(const float4*)(qg + (size_t)(nnA + 16) * QKVN + dA);
        float4 k0 = *(const float4*)(qg + DI + (size_t)nnA * QKVN + dA);
        float4 k1 = *(const float4*)(qg + DI + (size_t)(nnA + 16) * QKVN + dA);

        sq0 += q0.x * q0.x + q1.x * q1.x;
        sq1 += q0.y * q0.y + q1.y * q1.y;
        sq2 += q0.z * q0.z + q1.z * q1.z;
        sq3 += q0.w * q0.w + q1.w * q1.w;
        sk0 += k0.x * k0.x + k1.x * k1.x;
        sk1 += k0.y * k0.y + k1.y * k1.y;
        sk2 += k0.z * k0.z + k1.z * k1.z;
        sk3 += k0.w * k0.w + k1.w * k1.w;

        __syncthreads();
        *(float4*)&qs[nnA][dA] = q0;
        *(float4*)&qs[nnA + 16][dA] = q1;
        *(float4*)&ks[nnA][dA] = k0;
        *(float4*)&ks[nnA + 16][dA] = k1;
        __syncthreads();

        #pragma unroll 8
        for (int nn = 0; nn < 32; nn++) {
            float4 qa = *(const float4*)&qs[nn][ty * 4];
            float4 kb = *(const float4*)&ks[nn][tx * 4];
            float aa[4] = {qa.x, qa.y, qa.z, qa.w};
            float bb[4] = {kb.x, kb.y, kb.z, kb.w};
            #pragma unroll
            for (int i = 0; i < 4; i++)
                #pragma unroll
                for (int j = 0; j < 4; j++)
                    acc[i][j] = fmaf(aa[i], bb[j], acc[i][j]);
        }
    }

    float* simp = g_sim + bh * 4096;
    #pragma unroll
    for (int i = 0; i < 4; i++)
        #pragma unroll
        for (int j = 0; j < 4; j++)
            atomicAdd(&simp[(ty * 4 + i) * 64 + tx * 4 + j], acc[i][j]);

    atomicAdd(&g_ssq[bh * 64 + dA + 0], sq0);
    atomicAdd(&g_ssq[bh * 64 + dA + 1], sq1);
    atomicAdd(&g_ssq[bh * 64 + dA + 2], sq2);
    atomicAdd(&g_ssq[bh * 64 + dA + 3], sq3);
    atomicAdd(&g_ssk[bh * 64 + dA + 0], sk0);
    atomicAdd(&g_ssk[bh * 64 + dA + 1], sk1);
    atomicAdd(&g_ssk[bh * 64 + dA + 2], sk2);
    atomicAdd(&g_ssk[bh * 64 + dA + 3], sk3);
}

// ---------------- kernel 3b: scale + softmax over e ----------------
__global__ void k_softmax(const float* __restrict__ temperature) {
    const int bh = blockIdx.x;
    const int d = threadIdx.x;  // 64 threads
    const int h = bh & 15;
    const float tscale = 8.0f * expf(temperature[h]);

    __shared__ float rk[64];
    rk[d] = 1.0f / fmaxf(sqrtf(g_ssk[bh * 64 + d]), 1e-12f);
    __syncthreads();

    const float rq = 1.0f / fmaxf(sqrtf(g_ssq[bh * 64 + d]), 1e-12f);
    const float* srow = g_sim + bh * 4096 + d * 64;

    float s[64];
    float mx = -1e30f;
    #pragma unroll
    for (int e = 0; e < 64; e++) {
        s[e] = srow[e] * tscale * rq * rk[e];
        mx = fmaxf(mx, s[e]);
    }
    float sum = 0.0f;
    #pragma unroll
    for (int e = 0; e < 64; e++) {
        s[e] = expf(s[e] - mx);
        sum += s[e];
    }
    const float inv = 1.0f / sum;
    float* arow = g_attn + bh * 4096 + d * 64;
    #pragma unroll
    for (int e = 0; e < 64; e++) arow[e] = s[e] * inv;
}

// ---------------- kernel 3c: out[d][n] = sum_e attn[d][e] v[e][n]; write (b,n,h*64+d) ----------------
// 16 splits of 256 n each.
__global__ __launch_bounds__(256) void k_av() {
    const int bh = blockIdx.x;
    const int split = blockIdx.y;  // 0..15
    const int b = bh >> 4, h = bh & 15;
    const int tid = threadIdx.x;
    const int tx = tid & 15, ty = tid >> 4;

    __shared__ float at[64][68];  // attn transposed: at[e][d]
    __shared__ float vt[64][68];  // v transposed:    vt[e][nn]

    const float* ap = g_attn + bh * 4096;
    #pragma unroll
    for (int i = 0; i < 16; i++) {
        int idx = tid + i * 256;
        at[idx & 63][idx >> 6] = ap[idx];
    }

    const size_t vbase = ((size_t)b * SEQ) * QKVN + 2 * DI + (size_t)h * DH;

    for (int t = 0; t < 4; t++) {
        const int n0 = split * 256 + t * 64;
        __syncthreads();
        #pragma unroll
        for (int i = 0; i < 4; i++) {
            int f = tid + i * 256;
            int nn = f >> 4;
            int ec = (f & 15) * 4;
            float4 v4 = *(const float4*)(g_qkv + vbase + (size_t)(n0 + nn) * QKVN + ec);
            vt[ec + 0][nn] = v4.x;
            vt[ec + 1][nn] = v4.y;
            vt[ec + 2][nn] = v4.z;
            vt[ec + 3][nn] = v4.w;
        }
        __syncthreads();

        float acc[4][4];  // [nn j][d i]
        #pragma unroll
        for (int j = 0; j < 4; j++)
            #pragma unroll
            for (int i = 0; i < 4; i++) acc[j][i] = 0.0f;

        #pragma unroll 8
        for (int e = 0; e < 64; e++) {
            float4 a4 = *(const float4*)&at[e][tx * 4];  // d
            float4 v4 = *(const float4*)&vt[e][ty * 4];  // nn
            float aa[4] = {a4.x, a4.y, a4.z, a4.w};
            float vv[4] = {v4.x, v4.y, v4.z, v4.w};
            #pragma unroll
            for (int j = 0; j < 4; j++)
                #pragma unroll
                for (int i = 0; i < 4; i++)
                    acc[j][i] = fmaf(vv[j], aa[i], acc[j][i]);
        }

        #pragma unroll
        for (int j = 0; j < 4; j++) {
            int n = n0 + ty * 4 + j;
            float4 o = make_float4(acc[j][0], acc[j][1], acc[j][2], acc[j][3]);
            *(float4*)&g_ao[(size_t)(b * SEQ + n) * DI + h * DH + tx * 4] = o;
        }
    }
}

// ---------------- launch ----------------
extern "C" void kernel_launch(void* const* d_in, const int* in_sizes, int n_in,
                              void* d_out, int out_size) {
    const float* x = (const float*)d_in[0];
    const float* gamma = (const float*)d_in[1];
    const float* w_qkv = (const float*)d_in[2];
    const float* temperature = (const float*)d_in[3];
    const float* w_out = (const float*)d_in[4];
    float* out = (float*)d_out;

    k_rmsnorm<<<MROWS, 256>>>(x, gamma);
    k_gemm_qkv<<<dim3(QKVN / 128, MROWS / 128), 256>>>(w_qkv);
    k_sim<<<dim3(64, 16), 256>>>();
    k_softmax<<<64, 64>>>(temperature);
    k_av<<<dim3(64, 16), 256>>>();
    k_gemm_out<<<dim3(DI / 128, MROWS / 128), 256>>>(w_out, out);
}